// round 16
// baseline (speedup 1.0000x reference)
#include <cuda_runtime.h>
#include <cuda_fp16.h>
#include <math.h>
#include <stdint.h>

#define B_  8
#define LQ  2048
#define LA  2048
#define HD  1024

typedef __half h16;

// ---------------------------------------------------------------------------
// Scratch (static device arrays; allocation-free)
// ---------------------------------------------------------------------------
__device__ __align__(256) h16  g_wT_hi[HD * HD];
__device__ __align__(256) h16  g_wT_lo[HD * HD];
__device__ __align__(256) h16  g_q_hi[(size_t)B_ * LQ * HD];
__device__ __align__(256) h16  g_q_lo[(size_t)B_ * LQ * HD];
__device__ __align__(256) h16  g_qT_hi[(size_t)B_ * HD * LQ];
__device__ __align__(256) h16  g_qT_lo[(size_t)B_ * HD * LQ];
__device__ __align__(256) h16  g_a_hi[(size_t)B_ * LA * HD];
__device__ __align__(256) h16  g_a_lo[(size_t)B_ * LA * HD];
__device__ __align__(256) h16  g_G1_hi[(size_t)B_ * LQ * HD];
__device__ __align__(256) h16  g_G1_lo[(size_t)B_ * LQ * HD];
__device__ __align__(256) float g_G[(size_t)B_ * LA * LQ];      // logits^T [a,q]
__device__ __align__(256) h16  g_P_hi[(size_t)B_ * LA * LQ];
__device__ __align__(256) h16  g_P_lo[(size_t)B_ * LA * LQ];

// ---------------------------------------------------------------------------
// helpers
// ---------------------------------------------------------------------------
__device__ __forceinline__ uint32_t smem_u32(const void* p) {
    uint32_t a;
    asm("{ .reg .u64 t; cvta.to.shared.u64 t, %1; cvt.u32.u64 %0, t; }" : "=r"(a) : "l"(p));
    return a;
}
__device__ __forceinline__ void cp16(uint32_t dst, const void* src) {
    asm volatile("cp.async.cg.shared.global [%0], [%1], 16;" :: "r"(dst), "l"(src) : "memory");
}
#define CP_COMMIT() asm volatile("cp.async.commit_group;" ::: "memory")

__device__ __forceinline__ void ldsm_x4(uint32_t* r, uint32_t addr) {
    asm volatile("ldmatrix.sync.aligned.m8n8.x4.shared.b16 {%0,%1,%2,%3}, [%4];"
                 : "=r"(r[0]), "=r"(r[1]), "=r"(r[2]), "=r"(r[3]) : "r"(addr));
}
__device__ __forceinline__ void mma16816(float* c, const uint32_t* a, const uint32_t* b) {
    asm volatile(
        "mma.sync.aligned.m16n8k16.row.col.f32.f16.f16.f32 "
        "{%0,%1,%2,%3}, {%4,%5,%6,%7}, {%8,%9}, {%0,%1,%2,%3};"
        : "+f"(c[0]), "+f"(c[1]), "+f"(c[2]), "+f"(c[3])
        : "r"(a[0]), "r"(a[1]), "r"(a[2]), "r"(a[3]), "r"(b[0]), "r"(b[1]));
}

__device__ __forceinline__ void split2(float v, h16& h, h16& l) {
    h = __float2half_rn(v);
    l = __float2half_rn(v - __half2float(h));
}

// ---------------------------------------------------------------------------
// HMMA GEMM (NT): C[M,N] = sum_k (Ahi+Alo)[m,k]*(Bhi+Blo)[n,k]
// TERMS==3: AhBh + AhBl + AlBh.  TERMS==2: AhBh + AlBh (B-lo dropped).
// CTA 128x128, BK=64, 8 warps (2x4) of 64x32, 3-stage cp.async pipeline.
// Tail barrier overlaps kk3 MMAs; LDSM sub-bursts interleaved with the three
// 16-MMA term groups. Warp phase stagger: warp_m==1 warps run each kk-step's
// (part, mma-group) sequence in reverse so SMSP warp pairs de-phase their
// LDSM bursts against each other's MMA groups.
// EPI==0: C = acc + bias[n], split-stored fp16 hi/lo. EPI==1: fp32 store.
// ---------------------------------------------------------------------------
#define TILE_B  16384           // 128 rows x 64 halves x 2B
#define STAGE_B 65536           // 4 tiles (Ah, Al, Bh, Bl)

template<int EPI, int TERMS>
__global__ __launch_bounds__(256, 1) void mm_kernel(
    const h16* __restrict__ Ahi, const h16* __restrict__ Alo,
    const h16* __restrict__ Bhi, const h16* __restrict__ Blo,
    int K, long long sA, long long sB,
    const float* __restrict__ bias,
    float* __restrict__ Cf, long long sC, int ldc,
    h16* __restrict__ Chi, h16* __restrict__ Clo)
{
    extern __shared__ char dsm[];
    const int tid = threadIdx.x;
    const int wid = tid >> 5;
    const int lane = tid & 31;
    const int warp_m = wid >> 2;          // 0..1 (64 rows each)
    const int warp_n = wid & 3;           // 0..3 (32 cols each)
    const int z = blockIdx.z;
    const int bm0 = blockIdx.y * 128;
    const int bn0 = blockIdx.x * 128;

    const uint32_t sbase = (smem_u32(dsm) + 1023u) & ~1023u;

    const h16* pt[4] = {
        Ahi + (size_t)z * sA + (size_t)bm0 * K,
        Alo + (size_t)z * sA + (size_t)bm0 * K,
        Bhi + (size_t)z * sB + (size_t)bn0 * K,
        Blo + (size_t)z * sB + (size_t)bn0 * K };

    // fill one stage: tiles of 128 rows x 64 halves (128B), swizzle c^(row&7)
    auto fill = [&](int stage, int k0) {
        uint32_t sb = sbase + stage * STAGE_B;
        #pragma unroll
        for (int t = 0; t < 4; ++t) {
            if (TERMS == 2 && t == 3) continue;   // B-lo tile unused
            #pragma unroll
            for (int rpt = 0; rpt < 4; ++rpt) {
                int idx = rpt * 256 + tid;
                int row = idx >> 3, c = idx & 7;
                uint32_t phys = (uint32_t)(c ^ (row & 7));
                uint32_t dst = sb + t * TILE_B + row * 128 + phys * 16;
                cp16(dst, pt[t] + (size_t)row * K + k0 + c * 8);
            }
        }
        CP_COMMIT();
    };

    float acc[4][4][4];
    #pragma unroll
    for (int i = 0; i < 4; ++i)
        #pragma unroll
        for (int j = 0; j < 4; ++j)
            #pragma unroll
            for (int k = 0; k < 4; ++k) acc[i][j][k] = 0.f;

    const int NK = K >> 6;

    // ldsm lane mappings
    const int grp = lane >> 3;
    const int bro = warp_n * 32 + ((grp >> 1) & 1) * 8 + (lane & 7);
    const int gch = grp & 1;
    const int arow = warp_m * 64 + (lane & 15);
    const int ach = lane >> 4;

    // double-buffered fragments across kk steps
    uint32_t aH[2][4][4], aL[2][4][4], bH[2][8], bL[2][8];

    // fragment sub-burst loads (stage base stb, k16-step kk, buffer buf)
    auto part0 = [&](uint32_t stb, int kk, int buf) {       // aH: 4 ldsm
        const int ac = kk * 2 + ach;
        #pragma unroll
        for (int mt = 0; mt < 4; ++mt) {
            int row = arow + mt * 16;
            ldsm_x4(aH[buf][mt], stb + row * 128 + (uint32_t)(ac ^ (row & 7)) * 16);
        }
    };
    auto part1 = [&](uint32_t stb, int kk, int buf) {       // bH (+bL): 2(+2)
        const int bc = kk * 2 + gch;
        #pragma unroll
        for (int p = 0; p < 2; ++p) {
            int row = bro + p * 16;
            ldsm_x4(&bH[buf][p * 4],
                    stb + 2 * TILE_B + row * 128 + (uint32_t)(bc ^ (row & 7)) * 16);
        }
        if (TERMS == 3) {
            #pragma unroll
            for (int p = 0; p < 2; ++p) {
                int row = bro + p * 16;
                ldsm_x4(&bL[buf][p * 4],
                        stb + 3 * TILE_B + row * 128 + (uint32_t)(bc ^ (row & 7)) * 16);
            }
        }
    };
    auto part2 = [&](uint32_t stb, int kk, int buf) {       // aL: 4 ldsm
        const int ac = kk * 2 + ach;
        #pragma unroll
        for (int mt = 0; mt < 4; ++mt) {
            int row = arow + mt * 16;
            ldsm_x4(aL[buf][mt],
                    stb + TILE_B + row * 128 + (uint32_t)(ac ^ (row & 7)) * 16);
        }
    };
    auto mma_g0 = [&](int cur) {
        #pragma unroll
        for (int mt = 0; mt < 4; ++mt)
            #pragma unroll
            for (int nt = 0; nt < 4; ++nt)
                mma16816(acc[mt][nt], aH[cur][mt], &bH[cur][nt * 2]);
    };
    auto mma_g1 = [&](int cur) {
        #pragma unroll
        for (int mt = 0; mt < 4; ++mt)
            #pragma unroll
            for (int nt = 0; nt < 4; ++nt)
                mma16816(acc[mt][nt], aH[cur][mt], &bL[cur][nt * 2]);
    };
    auto mma_g2 = [&](int cur) {
        #pragma unroll
        for (int mt = 0; mt < 4; ++mt)
            #pragma unroll
            for (int nt = 0; nt < 4; ++nt)
                mma16816(acc[mt][nt], aL[cur][mt], &bH[cur][nt * 2]);
    };

    // prologue
    fill(0, 0);
    fill(1, 64);
    asm volatile("cp.async.wait_group 1;" ::: "memory");   // fill(0) done
    __syncthreads();
    part0(sbase, 0, 0);
    part1(sbase, 0, 0);
    part2(sbase, 0, 0);

    for (int i = 0; i < NK; ++i) {
        const uint32_t sb  = sbase + (i % 3) * STAGE_B;
        const uint32_t nsb = sbase + ((i + 1) % 3) * STAGE_B;
        if (i + 2 < NK) fill((i + 2) % 3, (i + 2) * 64);
        const bool more = (i + 1 < NK);

        if (warp_m == 0) {
            // forward phase order
            #pragma unroll
            for (int kk = 0; kk < 3; ++kk) {
                const int cur = kk & 1;
                const int nxt = cur ^ 1;
                part0(sb, kk + 1, nxt);
                mma_g0(cur);
                part1(sb, kk + 1, nxt);
                if (TERMS == 3) mma_g1(cur);
                part2(sb, kk + 1, nxt);
                mma_g2(cur);
            }
            {   // kk = 3 tail
                const int cur = 1, nxt = 0;
                if (more) {
                    if (i + 2 < NK) asm volatile("cp.async.wait_group 1;" ::: "memory");
                    else            asm volatile("cp.async.wait_group 0;" ::: "memory");
                    __syncthreads();
                    part0(nsb, 0, nxt);
                }
                mma_g0(cur);
                if (more) part1(nsb, 0, nxt);
                if (TERMS == 3) mma_g1(cur);
                if (more) part2(nsb, 0, nxt);
                mma_g2(cur);
            }
        } else {
            // reverse phase order (stagger against SMSP partner warp)
            #pragma unroll
            for (int kk = 0; kk < 3; ++kk) {
                const int cur = kk & 1;
                const int nxt = cur ^ 1;
                part2(sb, kk + 1, nxt);
                mma_g2(cur);
                part1(sb, kk + 1, nxt);
                if (TERMS == 3) mma_g1(cur);
                part0(sb, kk + 1, nxt);
                mma_g0(cur);
            }
            {   // kk = 3 tail
                const int cur = 1, nxt = 0;
                if (more) {
                    if (i + 2 < NK) asm volatile("cp.async.wait_group 1;" ::: "memory");
                    else            asm volatile("cp.async.wait_group 0;" ::: "memory");
                    __syncthreads();
                    part2(nsb, 0, nxt);
                }
                mma_g2(cur);
                if (more) part1(nsb, 0, nxt);
                if (TERMS == 3) mma_g1(cur);
                if (more) part0(nsb, 0, nxt);
                mma_g0(cur);
            }
        }
    }

    // epilogue
    #pragma unroll
    for (int mt = 0; mt < 4; ++mt) {
        #pragma unroll
        for (int nt = 0; nt < 4; ++nt) {
            const int m0 = bm0 + warp_m * 64 + mt * 16 + (lane >> 2);
            const int n0 = bn0 + warp_n * 32 + nt * 8 + 2 * (lane & 3);
            float* c = acc[mt][nt];
            if (EPI == 1) {
                float* r0 = Cf + (size_t)z * sC + (size_t)m0 * ldc + n0;
                float* r1 = Cf + (size_t)z * sC + (size_t)(m0 + 8) * ldc + n0;
                *(float2*)r0 = make_float2(c[0], c[1]);
                *(float2*)r1 = make_float2(c[2], c[3]);
            } else {
                float b0 = bias[n0], b1 = bias[n0 + 1];
                h16 h0, l0, h1, l1;
                split2(c[0] + b0, h0, l0); split2(c[1] + b1, h1, l1);
                *(__half2*)(Chi + (size_t)m0 * ldc + n0) = __halves2half2(h0, h1);
                *(__half2*)(Clo + (size_t)m0 * ldc + n0) = __halves2half2(l0, l1);
                split2(c[2] + b0, h0, l0); split2(c[3] + b1, h1, l1);
                *(__half2*)(Chi + (size_t)(m0 + 8) * ldc + n0) = __halves2half2(h0, h1);
                *(__half2*)(Clo + (size_t)(m0 + 8) * ldc + n0) = __halves2half2(l0, l1);
            }
        }
    }
}

// ---------------------------------------------------------------------------
// elementwise fp32 -> (hi, lo) fp16 split
// ---------------------------------------------------------------------------
__global__ __launch_bounds__(256) void split_kernel(
    const float4* __restrict__ in, __half2* __restrict__ hi,
    __half2* __restrict__ lo, int n4)
{
    int i = blockIdx.x * 256 + threadIdx.x;
    if (i >= n4) return;
    float4 v = in[i];
    h16 h0, l0, h1, l1, h2, l2, h3, l3;
    split2(v.x, h0, l0); split2(v.y, h1, l1);
    split2(v.z, h2, l2); split2(v.w, h3, l3);
    hi[2 * i + 0] = __halves2half2(h0, h1);
    hi[2 * i + 1] = __halves2half2(h2, h3);
    lo[2 * i + 0] = __halves2half2(l0, l1);
    lo[2 * i + 1] = __halves2half2(l2, l3);
}

// ---------------------------------------------------------------------------
// batched transpose + split: in [R, C] fp32 -> out [C, R] (hi, lo) fp16.
// If rh/rl nonnull also emits row-major split (single pass over input).
// ---------------------------------------------------------------------------
__global__ __launch_bounds__(256) void transpose_split_kernel(
    const float* __restrict__ in, h16* __restrict__ ohi, h16* __restrict__ olo,
    h16* __restrict__ rh, h16* __restrict__ rl, int R, int C)
{
    __shared__ float t[32][33];
    const size_t bofs = (size_t)blockIdx.z * R * C;
    const float* ip = in + bofs;
    const int c0 = blockIdx.x * 32, r0 = blockIdx.y * 32;
    const int x = threadIdx.x & 31;
    const int ty = threadIdx.x >> 5;   // 0..7
    #pragma unroll
    for (int dy = 0; dy < 32; dy += 8) {
        float v = ip[(size_t)(r0 + ty + dy) * C + c0 + x];
        t[ty + dy][x] = v;
        if (rh) {
            h16 h, l; split2(v, h, l);
            size_t ridx = bofs + (size_t)(r0 + ty + dy) * C + c0 + x;
            rh[ridx] = h;
            rl[ridx] = l;
        }
    }
    __syncthreads();
    #pragma unroll
    for (int dy = 0; dy < 32; dy += 8) {
        float v = t[x][ty + dy];
        h16 h, l; split2(v, h, l);
        size_t oidx = bofs + (size_t)(c0 + ty + dy) * R + r0 + x;
        ohi[oidx] = h;
        olo[oidx] = l;
    }
}

// ---------------------------------------------------------------------------
// row softmax over q (rows of G^T [B*LA, LQ]); writes split probs * 1/sum.
// ---------------------------------------------------------------------------
__global__ __launch_bounds__(256) void softmax_split_kernel(
    const float* __restrict__ G, h16* __restrict__ Phi, h16* __restrict__ Plo)
{
    __shared__ float red[256];
    const size_t row = blockIdx.x;
    const float4* g4 = (const float4*)(G + row * LQ);
    const int tid = threadIdx.x;

    float4 v[2];
    v[0] = g4[tid];
    v[1] = g4[tid + 256];

    float m = fmaxf(fmaxf(fmaxf(v[0].x, v[0].y), fmaxf(v[0].z, v[0].w)),
                    fmaxf(fmaxf(v[1].x, v[1].y), fmaxf(v[1].z, v[1].w)));
    red[tid] = m; __syncthreads();
    #pragma unroll
    for (int s = 128; s > 0; s >>= 1) {
        if (tid < s) red[tid] = fmaxf(red[tid], red[tid + s]);
        __syncthreads();
    }
    m = red[0]; __syncthreads();

    float ssum = 0.f;
    #pragma unroll
    for (int k = 0; k < 2; ++k) {
        v[k].x = __expf(v[k].x - m); ssum += v[k].x;
        v[k].y = __expf(v[k].y - m); ssum += v[k].y;
        v[k].z = __expf(v[k].z - m); ssum += v[k].z;
        v[k].w = __expf(v[k].w - m); ssum += v[k].w;
    }
    red[tid] = ssum; __syncthreads();
    #pragma unroll
    for (int s = 128; s > 0; s >>= 1) {
        if (tid < s) red[tid] += red[tid + s];
        __syncthreads();
    }
    const float inv = 1.0f / red[0];

    __half2* ph2 = (__half2*)(Phi + row * LQ);
    __half2* pl2 = (__half2*)(Plo + row * LQ);
    #pragma unroll
    for (int k = 0; k < 2; ++k) {
        int base = (tid + k * 256) * 2;
        h16 h0, l0, h1, l1;
        split2(v[k].x * inv, h0, l0); split2(v[k].y * inv, h1, l1);
        ph2[base] = __halves2half2(h0, h1);
        pl2[base] = __halves2half2(l0, l1);
        split2(v[k].z * inv, h0, l0); split2(v[k].w * inv, h1, l1);
        ph2[base + 1] = __halves2half2(h0, h1);
        pl2[base + 1] = __halves2half2(l0, l1);
    }
}

// ---------------------------------------------------------------------------
extern "C" void kernel_launch(void* const* d_in, const int* in_sizes, int n_in,
                              void* d_out, int out_size)
{
    const float* q    = (const float*)d_in[0];   // [B, LQ, HD]
    const float* a    = (const float*)d_in[1];   // [B, LA, HD]
    const float* w    = (const float*)d_in[2];   // [HD, HD]
    const float* bias = (const float*)d_in[3];   // [HD]
    float* out = (float*)d_out;                  // [B, LA, HD]
    (void)in_sizes; (void)n_in; (void)out_size;

    h16 *wTh, *wTl, *qh, *ql, *qTh, *qTl, *ah, *al, *g1h, *g1l, *ph, *pl;
    float* G;
    cudaGetSymbolAddress((void**)&wTh, g_wT_hi);
    cudaGetSymbolAddress((void**)&wTl, g_wT_lo);
    cudaGetSymbolAddress((void**)&qh,  g_q_hi);
    cudaGetSymbolAddress((void**)&ql,  g_q_lo);
    cudaGetSymbolAddress((void**)&qTh, g_qT_hi);
    cudaGetSymbolAddress((void**)&qTl, g_qT_lo);
    cudaGetSymbolAddress((void**)&ah,  g_a_hi);
    cudaGetSymbolAddress((void**)&al,  g_a_lo);
    cudaGetSymbolAddress((void**)&g1h, g_G1_hi);
    cudaGetSymbolAddress((void**)&g1l, g_G1_lo);
    cudaGetSymbolAddress((void**)&G,   g_G);
    cudaGetSymbolAddress((void**)&ph,  g_P_hi);
    cudaGetSymbolAddress((void**)&pl,  g_P_lo);

    const int dyn_smem = 3 * STAGE_B + 1024;
    cudaFuncSetAttribute(mm_kernel<0,3>, cudaFuncAttributeMaxDynamicSharedMemorySize, dyn_smem);
    cudaFuncSetAttribute(mm_kernel<1,3>, cudaFuncAttributeMaxDynamicSharedMemorySize, dyn_smem);
    cudaFuncSetAttribute(mm_kernel<1,2>, cudaFuncAttributeMaxDynamicSharedMemorySize, dyn_smem);

    // 1) input conversions
    {
        int n4 = (B_ * LQ * HD) / 4;
        split_kernel<<<n4 / 256, 256>>>((const float4*)a, (__half2*)ah, (__half2*)al, n4);
    }
    {
        dim3 grid(HD / 32, HD / 32, 1);
        transpose_split_kernel<<<grid, 256>>>(w, wTh, wTl, nullptr, nullptr, HD, HD);
    }
    {
        // fused: q -> qh/ql (row-major) + qTh/qTl (transposed), one pass
        dim3 grid(HD / 32, LQ / 32, B_);
        transpose_split_kernel<<<grid, 256>>>(q, qTh, qTl, qh, ql, LQ, HD);
    }

    // 2) G1 = q @ w + b  (M=B*LQ, N=HD, K=HD), split-stored fp16
    {
        dim3 grid(HD / 128, (B_ * LQ) / 128, 1);
        mm_kernel<0,3><<<grid, 256, dyn_smem>>>(qh, ql, wTh, wTl, HD, 0, 0,
                                                bias, nullptr, 0, HD, g1h, g1l);
    }
    // 3) G^T[a,q] = a @ G1^T  (per batch M=LA, N=LQ, K=HD), fp32
    {
        dim3 grid(LQ / 128, LA / 128, B_);
        mm_kernel<1,3><<<grid, 256, dyn_smem>>>(ah, al, g1h, g1l, HD,
                                                (long long)LA * HD, (long long)LQ * HD,
                                                nullptr, G, (long long)LA * LQ, LQ,
                                                nullptr, nullptr);
    }
    // 4) row softmax over q + split probs
    softmax_split_kernel<<<B_ * LA, 256>>>(G, ph, pl);

    // 5) out[a,h] = P[a,q] @ qT[h,q]^T  (per batch M=LA, N=HD, K=LQ),
    //    2-term (q_lo dropped), fp32
    {
        dim3 grid(HD / 128, LA / 128, B_);
        mm_kernel<1,2><<<grid, 256, dyn_smem>>>(ph, pl, qTh, qTl, LQ,
                                                (long long)LA * LQ, (long long)HD * LQ,
                                                nullptr, out, (long long)LA * HD, HD,
                                                nullptr, nullptr);
    }
}

// round 17
// speedup vs baseline: 1.0275x; 1.0275x over previous
#include <cuda_runtime.h>
#include <cuda_fp16.h>
#include <math.h>
#include <stdint.h>

#define B_  8
#define LQ  2048
#define LA  2048
#define HD  1024

typedef __half h16;

// ---------------------------------------------------------------------------
// Scratch (static device arrays; allocation-free)
// ---------------------------------------------------------------------------
__device__ __align__(256) h16  g_wT_hi[HD * HD];
__device__ __align__(256) h16  g_wT_lo[HD * HD];
__device__ __align__(256) h16  g_q_hi[(size_t)B_ * LQ * HD];
__device__ __align__(256) h16  g_q_lo[(size_t)B_ * LQ * HD];
__device__ __align__(256) h16  g_qT_hi[(size_t)B_ * HD * LQ];
__device__ __align__(256) h16  g_qT_lo[(size_t)B_ * HD * LQ];
__device__ __align__(256) h16  g_a_hi[(size_t)B_ * LA * HD];
__device__ __align__(256) h16  g_a_lo[(size_t)B_ * LA * HD];
__device__ __align__(256) h16  g_G1_hi[(size_t)B_ * LQ * HD];
__device__ __align__(256) h16  g_G1_lo[(size_t)B_ * LQ * HD];
__device__ __align__(256) float g_G[(size_t)B_ * LA * LQ];      // logits^T [a,q]
__device__ __align__(256) h16  g_P_hi[(size_t)B_ * LA * LQ];
__device__ __align__(256) h16  g_P_lo[(size_t)B_ * LA * LQ];

// ---------------------------------------------------------------------------
// helpers
// ---------------------------------------------------------------------------
__device__ __forceinline__ uint32_t smem_u32(const void* p) {
    uint32_t a;
    asm("{ .reg .u64 t; cvta.to.shared.u64 t, %1; cvt.u32.u64 %0, t; }" : "=r"(a) : "l"(p));
    return a;
}
__device__ __forceinline__ void cp16(uint32_t dst, const void* src) {
    asm volatile("cp.async.cg.shared.global [%0], [%1], 16;" :: "r"(dst), "l"(src) : "memory");
}
#define CP_COMMIT() asm volatile("cp.async.commit_group;" ::: "memory")

__device__ __forceinline__ void ldsm_x4(uint32_t* r, uint32_t addr) {
    asm volatile("ldmatrix.sync.aligned.m8n8.x4.shared.b16 {%0,%1,%2,%3}, [%4];"
                 : "=r"(r[0]), "=r"(r[1]), "=r"(r[2]), "=r"(r[3]) : "r"(addr));
}
__device__ __forceinline__ void mma16816(float* c, const uint32_t* a, const uint32_t* b) {
    asm volatile(
        "mma.sync.aligned.m16n8k16.row.col.f32.f16.f16.f32 "
        "{%0,%1,%2,%3}, {%4,%5,%6,%7}, {%8,%9}, {%0,%1,%2,%3};"
        : "+f"(c[0]), "+f"(c[1]), "+f"(c[2]), "+f"(c[3])
        : "r"(a[0]), "r"(a[1]), "r"(a[2]), "r"(a[3]), "r"(b[0]), "r"(b[1]));
}

__device__ __forceinline__ void split2(float v, h16& h, h16& l) {
    h = __float2half_rn(v);
    l = __float2half_rn(v - __half2float(h));
}

// ---------------------------------------------------------------------------
// HMMA GEMM (NT): C[M,N] = sum_k (Ahi+Alo)[m,k]*(Bhi+Blo)[n,k]
// TERMS==3: AhBh + AhBl + AlBh.  TERMS==2: AhBh + AlBh (B-lo dropped).
// CTA 128x64, 4 warps (2x2) of 64x32, BK=64, 2-stage double buffer,
// 97 KB smem/CTA -> 2 CTAs/SM so one CTA's barrier/wait overlaps the other
// CTA's MMAs. One __syncthreads per iteration (tail: wait_group 0 ->
// barrier -> refill consumed stage -> next-iter kk0 frag loads interleaved
// with kk3 MMAs). Fragments double-buffered across kk-steps.
// EPI==0: C = acc + bias[n], split-stored fp16 hi/lo. EPI==1: fp32 store.
// ---------------------------------------------------------------------------
#define A_TILE_B 16384          // 128 rows x 128B
#define B_TILE_B 8192           // 64 rows x 128B
#define STAGE_B  49152          // Ah + Al + Bh + Bl
#define NTHR     128

template<int EPI, int TERMS>
__global__ __launch_bounds__(NTHR, 2) void mm_kernel(
    const h16* __restrict__ Ahi, const h16* __restrict__ Alo,
    const h16* __restrict__ Bhi, const h16* __restrict__ Blo,
    int K, long long sA, long long sB,
    const float* __restrict__ bias,
    float* __restrict__ Cf, long long sC, int ldc,
    h16* __restrict__ Chi, h16* __restrict__ Clo)
{
    extern __shared__ char dsm[];
    const int tid = threadIdx.x;
    const int wid = tid >> 5;
    const int lane = tid & 31;
    const int warp_m = wid >> 1;          // 0..1 (64 rows each)
    const int warp_n = wid & 1;           // 0..1 (32 cols each)
    const int z = blockIdx.z;
    const int bm0 = blockIdx.y * 128;
    const int bn0 = blockIdx.x * 64;

    const uint32_t sbase = (smem_u32(dsm) + 1023u) & ~1023u;

    const h16* pA[2] = {
        Ahi + (size_t)z * sA + (size_t)bm0 * K,
        Alo + (size_t)z * sA + (size_t)bm0 * K };
    const h16* pB[2] = {
        Bhi + (size_t)z * sB + (size_t)bn0 * K,
        Blo + (size_t)z * sB + (size_t)bn0 * K };

    // fill one stage: A tiles 128 rows, B tiles 64 rows, 128B rows,
    // chunk swizzle c ^ (row & 7)
    auto fill = [&](int stage, int k0) {
        uint32_t sb = sbase + stage * STAGE_B;
        #pragma unroll
        for (int t = 0; t < 2; ++t) {
            #pragma unroll
            for (int rpt = 0; rpt < 8; ++rpt) {
                int idx = rpt * NTHR + tid;
                int row = idx >> 3, c = idx & 7;
                uint32_t dst = sb + t * A_TILE_B + row * 128
                             + (uint32_t)(c ^ (row & 7)) * 16;
                cp16(dst, pA[t] + (size_t)row * K + k0 + c * 8);
            }
        }
        #pragma unroll
        for (int t = 0; t < 2; ++t) {
            if (TERMS == 2 && t == 1) continue;   // B-lo unused
            #pragma unroll
            for (int rpt = 0; rpt < 4; ++rpt) {
                int idx = rpt * NTHR + tid;
                int row = idx >> 3, c = idx & 7;
                uint32_t dst = sb + 2 * A_TILE_B + t * B_TILE_B + row * 128
                             + (uint32_t)(c ^ (row & 7)) * 16;
                cp16(dst, pB[t] + (size_t)row * K + k0 + c * 8);
            }
        }
        CP_COMMIT();
    };

    float acc[4][4][4];
    #pragma unroll
    for (int i = 0; i < 4; ++i)
        #pragma unroll
        for (int j = 0; j < 4; ++j)
            #pragma unroll
            for (int k = 0; k < 4; ++k) acc[i][j][k] = 0.f;

    const int NK = K >> 6;

    // ldsm lane mappings
    const int grp = lane >> 3;
    const int bro = warp_n * 32 + ((grp >> 1) & 1) * 8 + (lane & 7);
    const int gch = grp & 1;
    const int arow = warp_m * 64 + (lane & 15);
    const int ach = lane >> 4;

    // double-buffered fragments across kk steps
    uint32_t aH[2][4][4], aL[2][4][4], bH[2][8], bL[2][8];

    // fragment sub-burst loads (stage base stb, k16-step kk, buffer buf)
    auto part0 = [&](uint32_t stb, int kk, int buf) {       // aH: 4 ldsm
        const int ac = kk * 2 + ach;
        #pragma unroll
        for (int mt = 0; mt < 4; ++mt) {
            int row = arow + mt * 16;
            ldsm_x4(aH[buf][mt], stb + row * 128 + (uint32_t)(ac ^ (row & 7)) * 16);
        }
    };
    auto part1 = [&](uint32_t stb, int kk, int buf) {       // bH (+bL): 2(+2)
        const int bc = kk * 2 + gch;
        #pragma unroll
        for (int p = 0; p < 2; ++p) {
            int row = bro + p * 16;
            ldsm_x4(&bH[buf][p * 4],
                    stb + 2 * A_TILE_B + row * 128 + (uint32_t)(bc ^ (row & 7)) * 16);
        }
        if (TERMS == 3) {
            #pragma unroll
            for (int p = 0; p < 2; ++p) {
                int row = bro + p * 16;
                ldsm_x4(&bL[buf][p * 4],
                        stb + 2 * A_TILE_B + B_TILE_B + row * 128
                        + (uint32_t)(bc ^ (row & 7)) * 16);
            }
        }
    };
    auto part2 = [&](uint32_t stb, int kk, int buf) {       // aL: 4 ldsm
        const int ac = kk * 2 + ach;
        #pragma unroll
        for (int mt = 0; mt < 4; ++mt) {
            int row = arow + mt * 16;
            ldsm_x4(aL[buf][mt],
                    stb + A_TILE_B + row * 128 + (uint32_t)(ac ^ (row & 7)) * 16);
        }
    };
    auto mma_g0 = [&](int cur) {
        #pragma unroll
        for (int mt = 0; mt < 4; ++mt)
            #pragma unroll
            for (int nt = 0; nt < 4; ++nt)
                mma16816(acc[mt][nt], aH[cur][mt], &bH[cur][nt * 2]);
    };
    auto mma_g1 = [&](int cur) {
        #pragma unroll
        for (int mt = 0; mt < 4; ++mt)
            #pragma unroll
            for (int nt = 0; nt < 4; ++nt)
                mma16816(acc[mt][nt], aH[cur][mt], &bL[cur][nt * 2]);
    };
    auto mma_g2 = [&](int cur) {
        #pragma unroll
        for (int mt = 0; mt < 4; ++mt)
            #pragma unroll
            for (int nt = 0; nt < 4; ++nt)
                mma16816(acc[mt][nt], aL[cur][mt], &bH[cur][nt * 2]);
    };

    // prologue: 2-stage double buffer
    fill(0, 0);
    fill(1, 64);
    asm volatile("cp.async.wait_group 1;" ::: "memory");   // fill(0) done
    __syncthreads();
    part0(sbase, 0, 0);
    part1(sbase, 0, 0);
    part2(sbase, 0, 0);

    for (int i = 0; i < NK; ++i) {
        const uint32_t sb  = sbase + (i & 1) * STAGE_B;
        const uint32_t nsb = sbase + ((i + 1) & 1) * STAGE_B;
        const bool more = (i + 1 < NK);

        // kk = 0..2: prefetch kk+1 fragments from sb, interleaved with kk MMAs
        #pragma unroll
        for (int kk = 0; kk < 3; ++kk) {
            const int cur = kk & 1;
            const int nxt = cur ^ 1;
            part0(sb, kk + 1, nxt);
            mma_g0(cur);
            part1(sb, kk + 1, nxt);
            if (TERMS == 3) mma_g1(cur);
            part2(sb, kk + 1, nxt);
            mma_g2(cur);
        }

        // kk = 3 tail: stage sb fully read (all its frag loads precede this).
        // wait for next stage, barrier, refill sb, then overlap next-iter kk0
        // frag loads with kk3 MMAs.
        {
            const int cur = 1, nxt = 0;
            if (more) {
                asm volatile("cp.async.wait_group 0;" ::: "memory"); // fill(i+1) done
                __syncthreads();                                     // sb reads done CTA-wide
                if (i + 2 < NK) fill(i & 1, (i + 2) * 64);           // refill sb
                part0(nsb, 0, nxt);
            }
            mma_g0(cur);
            if (more) part1(nsb, 0, nxt);
            if (TERMS == 3) mma_g1(cur);
            if (more) part2(nsb, 0, nxt);
            mma_g2(cur);
        }
    }

    // epilogue
    #pragma unroll
    for (int mt = 0; mt < 4; ++mt) {
        #pragma unroll
        for (int nt = 0; nt < 4; ++nt) {
            const int m0 = bm0 + warp_m * 64 + mt * 16 + (lane >> 2);
            const int n0 = bn0 + warp_n * 32 + nt * 8 + 2 * (lane & 3);
            float* c = acc[mt][nt];
            if (EPI == 1) {
                float* r0 = Cf + (size_t)z * sC + (size_t)m0 * ldc + n0;
                float* r1 = Cf + (size_t)z * sC + (size_t)(m0 + 8) * ldc + n0;
                *(float2*)r0 = make_float2(c[0], c[1]);
                *(float2*)r1 = make_float2(c[2], c[3]);
            } else {
                float b0 = bias[n0], b1 = bias[n0 + 1];
                h16 h0, l0, h1, l1;
                split2(c[0] + b0, h0, l0); split2(c[1] + b1, h1, l1);
                *(__half2*)(Chi + (size_t)m0 * ldc + n0) = __halves2half2(h0, h1);
                *(__half2*)(Clo + (size_t)m0 * ldc + n0) = __halves2half2(l0, l1);
                split2(c[2] + b0, h0, l0); split2(c[3] + b1, h1, l1);
                *(__half2*)(Chi + (size_t)(m0 + 8) * ldc + n0) = __halves2half2(h0, h1);
                *(__half2*)(Clo + (size_t)(m0 + 8) * ldc + n0) = __halves2half2(l0, l1);
            }
        }
    }
}

// ---------------------------------------------------------------------------
// elementwise fp32 -> (hi, lo) fp16 split
// ---------------------------------------------------------------------------
__global__ __launch_bounds__(256) void split_kernel(
    const float4* __restrict__ in, __half2* __restrict__ hi,
    __half2* __restrict__ lo, int n4)
{
    int i = blockIdx.x * 256 + threadIdx.x;
    if (i >= n4) return;
    float4 v = in[i];
    h16 h0, l0, h1, l1, h2, l2, h3, l3;
    split2(v.x, h0, l0); split2(v.y, h1, l1);
    split2(v.z, h2, l2); split2(v.w, h3, l3);
    hi[2 * i + 0] = __halves2half2(h0, h1);
    hi[2 * i + 1] = __halves2half2(h2, h3);
    lo[2 * i + 0] = __halves2half2(l0, l1);
    lo[2 * i + 1] = __halves2half2(l2, l3);
}

// ---------------------------------------------------------------------------
// batched transpose + split: in [R, C] fp32 -> out [C, R] (hi, lo) fp16.
// If rh/rl nonnull also emits row-major split (single pass over input).
// ---------------------------------------------------------------------------
__global__ __launch_bounds__(256) void transpose_split_kernel(
    const float* __restrict__ in, h16* __restrict__ ohi, h16* __restrict__ olo,
    h16* __restrict__ rh, h16* __restrict__ rl, int R, int C)
{
    __shared__ float t[32][33];
    const size_t bofs = (size_t)blockIdx.z * R * C;
    const float* ip = in + bofs;
    const int c0 = blockIdx.x * 32, r0 = blockIdx.y * 32;
    const int x = threadIdx.x & 31;
    const int ty = threadIdx.x >> 5;   // 0..7
    #pragma unroll
    for (int dy = 0; dy < 32; dy += 8) {
        float v = ip[(size_t)(r0 + ty + dy) * C + c0 + x];
        t[ty + dy][x] = v;
        if (rh) {
            h16 h, l; split2(v, h, l);
            size_t ridx = bofs + (size_t)(r0 + ty + dy) * C + c0 + x;
            rh[ridx] = h;
            rl[ridx] = l;
        }
    }
    __syncthreads();
    #pragma unroll
    for (int dy = 0; dy < 32; dy += 8) {
        float v = t[x][ty + dy];
        h16 h, l; split2(v, h, l);
        size_t oidx = bofs + (size_t)(c0 + ty + dy) * R + r0 + x;
        ohi[oidx] = h;
        olo[oidx] = l;
    }
}

// ---------------------------------------------------------------------------
// row softmax over q (rows of G^T [B*LA, LQ]); writes split probs * 1/sum.
// ---------------------------------------------------------------------------
__global__ __launch_bounds__(256) void softmax_split_kernel(
    const float* __restrict__ G, h16* __restrict__ Phi, h16* __restrict__ Plo)
{
    __shared__ float red[256];
    const size_t row = blockIdx.x;
    const float4* g4 = (const float4*)(G + row * LQ);
    const int tid = threadIdx.x;

    float4 v[2];
    v[0] = g4[tid];
    v[1] = g4[tid + 256];

    float m = fmaxf(fmaxf(fmaxf(v[0].x, v[0].y), fmaxf(v[0].z, v[0].w)),
                    fmaxf(fmaxf(v[1].x, v[1].y), fmaxf(v[1].z, v[1].w)));
    red[tid] = m; __syncthreads();
    #pragma unroll
    for (int s = 128; s > 0; s >>= 1) {
        if (tid < s) red[tid] = fmaxf(red[tid], red[tid + s]);
        __syncthreads();
    }
    m = red[0]; __syncthreads();

    float ssum = 0.f;
    #pragma unroll
    for (int k = 0; k < 2; ++k) {
        v[k].x = __expf(v[k].x - m); ssum += v[k].x;
        v[k].y = __expf(v[k].y - m); ssum += v[k].y;
        v[k].z = __expf(v[k].z - m); ssum += v[k].z;
        v[k].w = __expf(v[k].w - m); ssum += v[k].w;
    }
    red[tid] = ssum; __syncthreads();
    #pragma unroll
    for (int s = 128; s > 0; s >>= 1) {
        if (tid < s) red[tid] += red[tid + s];
        __syncthreads();
    }
    const float inv = 1.0f / red[0];

    __half2* ph2 = (__half2*)(Phi + row * LQ);
    __half2* pl2 = (__half2*)(Plo + row * LQ);
    #pragma unroll
    for (int k = 0; k < 2; ++k) {
        int base = (tid + k * 256) * 2;
        h16 h0, l0, h1, l1;
        split2(v[k].x * inv, h0, l0); split2(v[k].y * inv, h1, l1);
        ph2[base] = __halves2half2(h0, h1);
        pl2[base] = __halves2half2(l0, l1);
        split2(v[k].z * inv, h0, l0); split2(v[k].w * inv, h1, l1);
        ph2[base + 1] = __halves2half2(h0, h1);
        pl2[base + 1] = __halves2half2(l0, l1);
    }
}

// ---------------------------------------------------------------------------
extern "C" void kernel_launch(void* const* d_in, const int* in_sizes, int n_in,
                              void* d_out, int out_size)
{
    const float* q    = (const float*)d_in[0];   // [B, LQ, HD]
    const float* a    = (const float*)d_in[1];   // [B, LA, HD]
    const float* w    = (const float*)d_in[2];   // [HD, HD]
    const float* bias = (const float*)d_in[3];   // [HD]
    float* out = (float*)d_out;                  // [B, LA, HD]
    (void)in_sizes; (void)n_in; (void)out_size;

    h16 *wTh, *wTl, *qh, *ql, *qTh, *qTl, *ah, *al, *g1h, *g1l, *ph, *pl;
    float* G;
    cudaGetSymbolAddress((void**)&wTh, g_wT_hi);
    cudaGetSymbolAddress((void**)&wTl, g_wT_lo);
    cudaGetSymbolAddress((void**)&qh,  g_q_hi);
    cudaGetSymbolAddress((void**)&ql,  g_q_lo);
    cudaGetSymbolAddress((void**)&qTh, g_qT_hi);
    cudaGetSymbolAddress((void**)&qTl, g_qT_lo);
    cudaGetSymbolAddress((void**)&ah,  g_a_hi);
    cudaGetSymbolAddress((void**)&al,  g_a_lo);
    cudaGetSymbolAddress((void**)&g1h, g_G1_hi);
    cudaGetSymbolAddress((void**)&g1l, g_G1_lo);
    cudaGetSymbolAddress((void**)&G,   g_G);
    cudaGetSymbolAddress((void**)&ph,  g_P_hi);
    cudaGetSymbolAddress((void**)&pl,  g_P_lo);

    const int dyn_smem = 2 * STAGE_B + 1024;     // 99328 B -> 2 CTAs/SM
    cudaFuncSetAttribute(mm_kernel<0,3>, cudaFuncAttributeMaxDynamicSharedMemorySize, dyn_smem);
    cudaFuncSetAttribute(mm_kernel<1,3>, cudaFuncAttributeMaxDynamicSharedMemorySize, dyn_smem);
    cudaFuncSetAttribute(mm_kernel<1,2>, cudaFuncAttributeMaxDynamicSharedMemorySize, dyn_smem);

    // 1) input conversions
    {
        int n4 = (B_ * LQ * HD) / 4;
        split_kernel<<<n4 / 256, 256>>>((const float4*)a, (__half2*)ah, (__half2*)al, n4);
    }
    {
        dim3 grid(HD / 32, HD / 32, 1);
        transpose_split_kernel<<<grid, 256>>>(w, wTh, wTl, nullptr, nullptr, HD, HD);
    }
    {
        // fused: q -> qh/ql (row-major) + qTh/qTl (transposed), one pass
        dim3 grid(HD / 32, LQ / 32, B_);
        transpose_split_kernel<<<grid, 256>>>(q, qTh, qTl, qh, ql, LQ, HD);
    }

    // 2) G1 = q @ w + b  (M=B*LQ, N=HD, K=HD), split-stored fp16
    {
        dim3 grid(HD / 64, (B_ * LQ) / 128, 1);
        mm_kernel<0,3><<<grid, NTHR, dyn_smem>>>(qh, ql, wTh, wTl, HD, 0, 0,
                                                 bias, nullptr, 0, HD, g1h, g1l);
    }
    // 3) G^T[a,q] = a @ G1^T  (per batch M=LA, N=LQ, K=HD), fp32
    {
        dim3 grid(LQ / 64, LA / 128, B_);
        mm_kernel<1,3><<<grid, NTHR, dyn_smem>>>(ah, al, g1h, g1l, HD,
                                                 (long long)LA * HD, (long long)LQ * HD,
                                                 nullptr, G, (long long)LA * LQ, LQ,
                                                 nullptr, nullptr);
    }
    // 4) row softmax over q + split probs
    softmax_split_kernel<<<B_ * LA, 256>>>(G, ph, pl);

    // 5) out[a,h] = P[a,q] @ qT[h,q]^T  (per batch M=LA, N=HD, K=LQ),
    //    2-term (q_lo dropped), fp32
    {
        dim3 grid(HD / 64, LA / 128, B_);
        mm_kernel<1,2><<<grid, NTHR, dyn_smem>>>(ph, pl, qTh, qTl, LQ,
                                                 (long long)LA * LQ, (long long)HD * LQ,
                                                 nullptr, out, (long long)LA * HD, HD,
                                                 nullptr, nullptr);
    }
}